// round 10
// baseline (speedup 1.0000x reference)
#include <cuda_runtime.h>
#include <cuda_bf16.h>
#include <math.h>

// Problem constants
#define Bsz 64
#define Tsz 512
#define Vsz 256
#define Hsz 1024
#define G3  3072   // 3*H
#define NBLK 128

#define SWPAD 1032       // W strip row stride (bf16) -> ldmatrix conflict-free
#define CHPAD 40         // h k32-chunk row stride (bf16) = 80B -> conflict-free
#define CHBUF (64 * CHPAD)   // one (grp,buf,arr) chunk buffer (bf16 elems)
#define GHS   25
// SMEM: W hi/lo (99072) + h [4 grp][2 buf][2 arr][64*CHPAD] (81920) + ghs[4][64*GHS] (25600)
#define SCAN_SMEM_B (24*SWPAD*2*2 + 4*2*2*CHBUF*2 + 4*64*GHS*4)   // 206592 B

typedef unsigned long long ull;

// ---------------- mma.sync helpers ------------------------------------------
__device__ __forceinline__ void mma_bf16(float* c, const unsigned* a, const unsigned* b) {
    asm volatile(
        "mma.sync.aligned.m16n8k16.row.col.f32.bf16.bf16.f32 "
        "{%0,%1,%2,%3}, {%4,%5,%6,%7}, {%8,%9}, {%0,%1,%2,%3};\n"
        : "+f"(c[0]), "+f"(c[1]), "+f"(c[2]), "+f"(c[3])
        : "r"(a[0]), "r"(a[1]), "r"(a[2]), "r"(a[3]), "r"(b[0]), "r"(b[1]));
}
__device__ __forceinline__ void ldsm4(unsigned* r, const void* p) {
    unsigned a = (unsigned)__cvta_generic_to_shared(p);
    asm volatile("ldmatrix.sync.aligned.m8n8.x4.shared.b16 {%0,%1,%2,%3}, [%4];"
                 : "=r"(r[0]), "=r"(r[1]), "=r"(r[2]), "=r"(r[3]) : "r"(a));
}
__device__ __forceinline__ unsigned pack_bf16x2(__nv_bfloat16 a, __nv_bfloat16 b) {
    __nv_bfloat162 t; t.x = a; t.y = b;
    return *(unsigned*)&t;
}

// packed fp32x2 FMA (kept for the fp32 M0 GEMM)
__device__ __forceinline__ void ffma2(ull& d, ull a, ull b) {
    asm("fma.rn.f32x2 %0, %1, %2, %0;" : "+l"(d) : "l"(a), "l"(b));
}
__device__ __forceinline__ ull pack_rep(float v) {
    ull r; unsigned u = __float_as_uint(v);
    asm("mov.b64 %0, {%1, %1};" : "=l"(r) : "r"(u));
    return r;
}
__device__ __forceinline__ float2 unpack2(ull v) {
    float2 r;
    asm("mov.b64 {%0, %1}, %2;" : "=f"(r.x), "=f"(r.y) : "l"(v));
    return r;
}

// ---------------- scratch (static __device__, no allocations) ----------------
__device__ float g_M0[(size_t)Vsz * G3];
__device__ float g_gx[(size_t)Bsz * Tsz * G3];
__device__ __nv_bfloat16 g_yHi[(size_t)Bsz * Tsz * Hsz];
__device__ __nv_bfloat16 g_yLo[(size_t)Bsz * Tsz * Hsz];
__device__ float g_hFA[Bsz * Hsz];
__device__ float g_hFB[Bsz * Hsz];
__device__ __nv_bfloat16 g_hHiA[Bsz * Hsz], g_hHiB[Bsz * Hsz];
__device__ __nv_bfloat16 g_hLoA[Bsz * Hsz], g_hLoB[Bsz * Hsz];
__device__ unsigned g_bar;

// ---------------- h0 init: fp32 copy + bf16 hi/lo split ----------------------
__global__ __launch_bounds__(256) void hinit_kernel(
    const float* __restrict__ src, float* __restrict__ hf,
    __nv_bfloat16* __restrict__ hhi, __nv_bfloat16* __restrict__ hlo)
{
    int i = blockIdx.x * 256 + threadIdx.x;
    float f = src[i];
    hf[i] = f;
    __nv_bfloat16 h = __float2bfloat16(f);
    hhi[i] = h;
    hlo[i] = __float2bfloat16(f - __bfloat162float(h));
}

// ---------------- fp32 GEMM 128x128x16, f32x2 (M0 only; also zeroes g_bar) ---
__global__ __launch_bounds__(256, 2) void gemm_tn_128(
    const float* __restrict__ A, const float* __restrict__ B,
    const float* __restrict__ bias, float* __restrict__ C,
    int M, int N, int K)
{
    if (blockIdx.x == 0 && blockIdx.y == 0 && threadIdx.x == 0) g_bar = 0u;

    __shared__ float As[16 * 128];
    __shared__ float Bs[16 * 128];
    const int tid = threadIdx.x;
    const int m0 = blockIdx.y * 128;
    const int n0 = blockIdx.x * 128;
    const int ty = tid >> 4;
    const int tx = tid & 15;
    const int lr = tid >> 1;
    const int lk = (tid & 1) << 3;

    const float* Ap = A + (size_t)(m0 + lr) * K + lk;
    const float* Bp = B + (size_t)(n0 + lr) * K + lk;

    ull acc[8][4];
#pragma unroll
    for (int i = 0; i < 8; ++i)
#pragma unroll
        for (int j = 0; j < 4; ++j) acc[i][j] = 0ull;

    float4 pa0 = *(const float4*)Ap;
    float4 pa1 = *(const float4*)(Ap + 4);
    float4 pb0 = *(const float4*)Bp;
    float4 pb1 = *(const float4*)(Bp + 4);

    const int nch = K >> 4;
    for (int c = 0; c < nch; ++c) {
        As[(lk + 0) * 128 + lr] = pa0.x; As[(lk + 1) * 128 + lr] = pa0.y;
        As[(lk + 2) * 128 + lr] = pa0.z; As[(lk + 3) * 128 + lr] = pa0.w;
        As[(lk + 4) * 128 + lr] = pa1.x; As[(lk + 5) * 128 + lr] = pa1.y;
        As[(lk + 6) * 128 + lr] = pa1.z; As[(lk + 7) * 128 + lr] = pa1.w;
        Bs[(lk + 0) * 128 + lr] = pb0.x; Bs[(lk + 1) * 128 + lr] = pb0.y;
        Bs[(lk + 2) * 128 + lr] = pb0.z; Bs[(lk + 3) * 128 + lr] = pb0.w;
        Bs[(lk + 4) * 128 + lr] = pb1.x; Bs[(lk + 5) * 128 + lr] = pb1.y;
        Bs[(lk + 6) * 128 + lr] = pb1.z; Bs[(lk + 7) * 128 + lr] = pb1.w;
        __syncthreads();
        if (c + 1 < nch) {
            pa0 = *(const float4*)(Ap + (c + 1) * 16);
            pa1 = *(const float4*)(Ap + (c + 1) * 16 + 4);
            pb0 = *(const float4*)(Bp + (c + 1) * 16);
            pb1 = *(const float4*)(Bp + (c + 1) * 16 + 4);
        }
#pragma unroll
        for (int k = 0; k < 16; ++k) {
            float4 a0 = *(const float4*)&As[k * 128 + (ty << 2)];
            float4 a1 = *(const float4*)&As[k * 128 + (ty << 2) + 64];
            ulonglong2 b0 = *(const ulonglong2*)&Bs[k * 128 + (tx << 2)];
            ulonglong2 b1 = *(const ulonglong2*)&Bs[k * 128 + (tx << 2) + 64];
            ull ap[8];
            ap[0] = pack_rep(a0.x); ap[1] = pack_rep(a0.y);
            ap[2] = pack_rep(a0.z); ap[3] = pack_rep(a0.w);
            ap[4] = pack_rep(a1.x); ap[5] = pack_rep(a1.y);
            ap[6] = pack_rep(a1.z); ap[7] = pack_rep(a1.w);
#pragma unroll
            for (int i = 0; i < 8; ++i) {
                ffma2(acc[i][0], ap[i], b0.x);
                ffma2(acc[i][1], ap[i], b0.y);
                ffma2(acc[i][2], ap[i], b1.x);
                ffma2(acc[i][3], ap[i], b1.y);
            }
        }
        __syncthreads();
    }

    float bb[8];
#pragma unroll
    for (int j = 0; j < 4; ++j) {
        bb[j]     = bias[n0 + (tx << 2) + j];
        bb[4 + j] = bias[n0 + (tx << 2) + 64 + j];
    }
#pragma unroll
    for (int i = 0; i < 8; ++i) {
        int row = m0 + (ty << 2) + (i & 3) + ((i >> 2) << 6);
        float* Cp = C + (size_t)row * N + n0 + (tx << 2);
        float2 c0 = unpack2(acc[i][0]);
        float2 c1 = unpack2(acc[i][1]);
        float2 c2 = unpack2(acc[i][2]);
        float2 c3 = unpack2(acc[i][3]);
        float4 v0 = make_float4(c0.x + bb[0], c0.y + bb[1], c1.x + bb[2], c1.y + bb[3]);
        float4 v1 = make_float4(c2.x + bb[4], c2.y + bb[5], c3.x + bb[6], c3.y + bb[7]);
        *(float4*)Cp = v0;
        *(float4*)(Cp + 64) = v1;
    }
}

// ---------------- gx0 gather: gx0[bt, g] = M0T[X[bt], g] ---------------------
__global__ __launch_bounds__(256) void gx0_fill_kernel(const int* __restrict__ X)
{
    size_t idx = (size_t)blockIdx.x * 256 + threadIdx.x;
    int bt = (int)(idx / (G3 / 4));
    int gq = (int)(idx % (G3 / 4));
    int tok = X[bt];
    float4 v = ((const float4*)g_M0)[(size_t)tok * (G3 / 4) + gq];
    ((float4*)g_gx)[idx] = v;
}

// ---------------- bf16-split MMA GEMM: C[M,N] = Y @ B^T + bias ---------------
__global__ __launch_bounds__(256) void mma_gemm(
    const __nv_bfloat16* __restrict__ Ahi, const __nv_bfloat16* __restrict__ Alo,
    const float* __restrict__ B, const float* __restrict__ bias,
    float* __restrict__ C, int M, int N, int remapA)
{
    __shared__ __nv_bfloat16 sAhi[128 * 40], sAlo[128 * 40];
    __shared__ __nv_bfloat16 sBhi[64 * 40],  sBlo[64 * 40];
    const int tid = threadIdx.x, wid = tid >> 5, lane = tid & 31;
    const int m0 = blockIdx.y * 128, n0 = blockIdx.x * 64;
    const int wm = wid & 3, wn = wid >> 2;

    float acc[2][4][4];
#pragma unroll
    for (int mt = 0; mt < 2; ++mt)
#pragma unroll
        for (int nt = 0; nt < 4; ++nt)
#pragma unroll
            for (int q = 0; q < 4; ++q) acc[mt][nt][q] = 0.f;

    for (int c = 0; c < 32; ++c) {
        const int k0 = c * 32;
#pragma unroll
        for (int s = 0; s < 4; ++s) {
            int i = tid + s * 256;
            int arr = i >> 9, e = i & 511, row = e >> 2, q = e & 3;
            int r = m0 + row; if (r >= M) r = M - 1;
            if (remapA) r = (r / (Tsz - 1)) * Tsz + (r % (Tsz - 1));
            const __nv_bfloat16* src = arr ? Alo : Ahi;
            uint4 v = *(const uint4*)(src + (size_t)r * Hsz + k0 + q * 8);
            __nv_bfloat16* dst = (arr ? sAlo : sAhi) + row * 40 + q * 8;
            *(uint4*)dst = v;
        }
#pragma unroll
        for (int s = 0; s < 2; ++s) {
            int i = tid + s * 256;
            int row = i >> 3, q = i & 7;
            float4 v = *(const float4*)(B + (size_t)(n0 + row) * Hsz + k0 + q * 4);
            __nv_bfloat16 h0 = __float2bfloat16(v.x), h1 = __float2bfloat16(v.y);
            __nv_bfloat16 h2 = __float2bfloat16(v.z), h3 = __float2bfloat16(v.w);
            __nv_bfloat16 l0 = __float2bfloat16(v.x - __bfloat162float(h0));
            __nv_bfloat16 l1 = __float2bfloat16(v.y - __bfloat162float(h1));
            __nv_bfloat16 l2 = __float2bfloat16(v.z - __bfloat162float(h2));
            __nv_bfloat16 l3 = __float2bfloat16(v.w - __bfloat162float(h3));
            unsigned* dh = (unsigned*)(sBhi + row * 40 + q * 4);
            dh[0] = pack_bf16x2(h0, h1); dh[1] = pack_bf16x2(h2, h3);
            unsigned* dl = (unsigned*)(sBlo + row * 40 + q * 4);
            dl[0] = pack_bf16x2(l0, l1); dl[1] = pack_bf16x2(l2, l3);
        }
        __syncthreads();

        unsigned bh[4][4], bl[4][4];
#pragma unroll
        for (int nt = 0; nt < 4; ++nt) {
            const int brow = wn * 32 + nt * 8 + (lane & 7);
            ldsm4(bh[nt], sBhi + brow * 40 + ((lane >> 3) << 3));
            ldsm4(bl[nt], sBlo + brow * 40 + ((lane >> 3) << 3));
        }
#pragma unroll
        for (int kk = 0; kk < 2; ++kk) {
            unsigned ah[2][4], al[2][4];
#pragma unroll
            for (int mt = 0; mt < 2; ++mt) {
                const int aoff = (wm * 32 + mt * 16 + (lane & 15)) * 40 + kk * 16 + ((lane >> 4) << 3);
                ldsm4(ah[mt], sAhi + aoff);
                ldsm4(al[mt], sAlo + aoff);
            }
#pragma unroll
            for (int mt = 0; mt < 2; ++mt)
#pragma unroll
                for (int nt = 0; nt < 4; ++nt) {
                    mma_bf16(acc[mt][nt], ah[mt], bh[nt] + 2 * kk);
                    mma_bf16(acc[mt][nt], ah[mt], bl[nt] + 2 * kk);
                    mma_bf16(acc[mt][nt], al[mt], bh[nt] + 2 * kk);
                }
        }
        __syncthreads();
    }

#pragma unroll
    for (int mt = 0; mt < 2; ++mt)
#pragma unroll
        for (int nt = 0; nt < 4; ++nt) {
            int r0 = m0 + wm * 32 + mt * 16 + (lane >> 2);
            int cb = n0 + wn * 32 + nt * 8 + 2 * (lane & 3);
            float b0 = bias[cb], b1 = bias[cb + 1];
            if (r0 < M) {
                C[(size_t)r0 * N + cb]     = acc[mt][nt][0] + b0;
                C[(size_t)r0 * N + cb + 1] = acc[mt][nt][1] + b1;
            }
            int r1 = r0 + 8;
            if (r1 < M) {
                C[(size_t)r1 * N + cb]     = acc[mt][nt][2] + b0;
                C[(size_t)r1 * N + cb + 1] = acc[mt][nt][3] + b1;
            }
        }
}

// ---------------- persistent GRU scan (m2 x k4, group barriers, bf16 MMA) ----
// 8 warps = 2 m-halves (m32) x 4 k-quarters (k256). Each warp: all 3 gates.
// W fragments 2x redundant (was 4x); A once. Staging per 64-thread k-group
// with named barriers. 4 k-partials reduced in the gate phase.
__global__ __launch_bounds__(256) void gru_scan_mma(
    const float* __restrict__ Whh, const float* __restrict__ bhh,
    const float* __restrict__ gx,
    __nv_bfloat16* __restrict__ yHi, __nv_bfloat16* __restrict__ yLo,
    float* __restrict__ hfA, float* __restrict__ hfB,
    __nv_bfloat16* __restrict__ hHiA, __nv_bfloat16* __restrict__ hHiB,
    __nv_bfloat16* __restrict__ hLoA, __nv_bfloat16* __restrict__ hLoB,
    int t_base)
{
    extern __shared__ __align__(16) unsigned char smraw[];
    __nv_bfloat16* sWhi = (__nv_bfloat16*)smraw;            // [24][SWPAD]
    __nv_bfloat16* sWlo = sWhi + 24 * SWPAD;
    __nv_bfloat16* sH   = sWlo + 24 * SWPAD;                // [4 grp][2 buf][2 arr][CHBUF]
    float* ghs = (float*)(sH + 16 * CHBUF);                 // [4][64*GHS]

    const int tid = threadIdx.x, wid = tid >> 5, lane = tid & 31;
    const int c0 = blockIdx.x << 3;
    const int mw = wid & 1, kc = wid >> 1;
    const int gtid = tid & 63, grp = tid >> 6;              // staging group == kc

    // Convert W strip to bf16 hi/lo in SMEM once per layer.
    for (int i = tid; i < 24 * 1024; i += 256) {
        int r = i >> 10, k = i & 1023;
        int g = r >> 3, jj = r & 7;
        float f = Whh[(size_t)(g * Hsz + c0 + jj) * Hsz + k];
        __nv_bfloat16 h = __float2bfloat16(f);
        sWhi[r * SWPAD + k] = h;
        sWlo[r * SWPAD + k] = __float2bfloat16(f - __bfloat162float(h));
    }
    const int gy = tid >> 3, gxc = tid & 7;
    const int jcol = c0 + gxc;
    const float br = bhh[jcol];
    const float bz = bhh[Hsz + jcol];
    const float bn = bhh[2 * Hsz + jcol];
    __syncthreads();

    for (int t = 0; t < Tsz; ++t) {
        const int par = t & 1;
        const float* hfIn  = par ? hfB : hfA;
        float*       hfOut = par ? hfA : hfB;
        const __nv_bfloat16* hHiIn = par ? hHiB : hHiA;
        const __nv_bfloat16* hLoIn = par ? hLoB : hLoA;
        __nv_bfloat16* hHiOut = par ? hHiA : hHiB;
        __nv_bfloat16* hLoOut = par ? hLoA : hLoB;

        const int kq0 = kc * 256;                 // this group's k base

        uint4 stg[8];
        // stage chunk 0 (k32) of this group's k-quarter
#pragma unroll
        for (int s = 0; s < 8; ++s) {
            int idx = gtid + s * 64;              // 0..511
            int arr = idx >> 8, e = idx & 255, row = e >> 2, q = e & 3;
            const __nv_bfloat16* src = arr ? hLoIn : hHiIn;
            stg[s] = __ldcg((const uint4*)(src + (size_t)row * Hsz + kq0) + q);
        }
        // prefetch gate preacts + h_old (consumed at end of step)
        float pxr[2], pxz[2], pxn[2], phold[2];
#pragma unroll
        for (int r = 0; r < 2; ++r) {
            const int b = gy + (r << 5);
            const float* gxr = gx + ((size_t)b * Tsz + t) * G3;
            pxr[r] = __ldcg(gxr + jcol);
            pxz[r] = __ldcg(gxr + Hsz + jcol);
            pxn[r] = __ldcg(gxr + 2 * Hsz + jcol);
            phold[r] = hfIn[(size_t)b * Hsz + jcol];
        }
#pragma unroll
        for (int s = 0; s < 8; ++s) {
            int idx = gtid + s * 64;
            int arr = idx >> 8, e = idx & 255, row = e >> 2, q = e & 3;
            __nv_bfloat16* dst = sH + ((grp * 2 + 0) * 2 + arr) * CHBUF + row * CHPAD + q * 8;
            *(uint4*)dst = stg[s];
        }
        asm volatile("bar.sync %0, 64;" :: "r"(grp + 1) : "memory");

        float accP[2][3][4], accQ[2][3][4];
#pragma unroll
        for (int mt = 0; mt < 2; ++mt)
#pragma unroll
            for (int g = 0; g < 3; ++g)
#pragma unroll
                for (int q = 0; q < 4; ++q) { accP[mt][g][q] = 0.f; accQ[mt][g][q] = 0.f; }

        for (int it = 0; it < 8; ++it) {
            if (it < 7) {
#pragma unroll
                for (int s = 0; s < 8; ++s) {
                    int idx = gtid + s * 64;
                    int arr = idx >> 8, e = idx & 255, row = e >> 2, q = e & 3;
                    const __nv_bfloat16* src = arr ? hLoIn : hHiIn;
                    stg[s] = __ldcg((const uint4*)(src + (size_t)row * Hsz + kq0 + (it + 1) * 32) + q);
                }
            }
            const int buf = it & 1;
            const __nv_bfloat16* Hh = sH + ((grp * 2 + buf) * 2 + 0) * CHBUF;
            const __nv_bfloat16* Hl = sH + ((grp * 2 + buf) * 2 + 1) * CHBUF;
            const int kbase = kq0 + it * 32;

            unsigned bh[3][4], bl[3][4];
#pragma unroll
            for (int g = 0; g < 3; ++g) {
                const int woff = (g * 8 + (lane & 7)) * SWPAD + kbase + ((lane >> 3) << 3);
                ldsm4(bh[g], sWhi + woff);
                ldsm4(bl[g], sWlo + woff);
            }
#pragma unroll
            for (int kk = 0; kk < 2; ++kk) {
#pragma unroll
                for (int mt = 0; mt < 2; ++mt) {
                    unsigned ah[4], al[4];
                    const int aoff = (mw * 32 + mt * 16 + (lane & 15)) * CHPAD
                                   + kk * 16 + ((lane >> 4) << 3);
                    ldsm4(ah, Hh + aoff);
                    ldsm4(al, Hl + aoff);
#pragma unroll
                    for (int g = 0; g < 3; ++g) {
                        mma_bf16(accP[mt][g], ah, bh[g] + 2 * kk);
                        mma_bf16(accQ[mt][g], ah, bl[g] + 2 * kk);
                        mma_bf16(accQ[mt][g], al, bh[g] + 2 * kk);
                    }
                }
            }
            if (it < 7) {
#pragma unroll
                for (int s = 0; s < 8; ++s) {
                    int idx = gtid + s * 64;
                    int arr = idx >> 8, e = idx & 255, row = e >> 2, q = e & 3;
                    __nv_bfloat16* dst = sH + ((grp * 2 + ((it + 1) & 1)) * 2 + arr) * CHBUF
                                       + row * CHPAD + q * 8;
                    *(uint4*)dst = stg[s];
                }
                asm volatile("bar.sync %0, 64;" :: "r"(grp + 1) : "memory");
            }
        }

        // write k-partial gh preacts to SMEM
        {
            float* gp = ghs + kc * 64 * GHS;
#pragma unroll
            for (int mt = 0; mt < 2; ++mt) {
                int row = mw * 32 + mt * 16 + (lane >> 2);
#pragma unroll
                for (int g = 0; g < 3; ++g) {
                    int gcol = g * 8 + 2 * (lane & 3);
                    gp[row * GHS + gcol]           = accP[mt][g][0] + accQ[mt][g][0];
                    gp[row * GHS + gcol + 1]       = accP[mt][g][1] + accQ[mt][g][1];
                    gp[(row + 8) * GHS + gcol]     = accP[mt][g][2] + accQ[mt][g][2];
                    gp[(row + 8) * GHS + gcol + 1] = accP[mt][g][3] + accQ[mt][g][3];
                }
            }
        }
        __syncthreads();

        // gates + state update (all 256 threads; sum 4 k-partials)
        {
#pragma unroll
            for (int r = 0; r < 2; ++r) {
                const int b = gy + (r << 5);
                float a0 = 0.f, a1 = 0.f, a2 = 0.f;
#pragma unroll
                for (int p = 0; p < 4; ++p) {
                    const float* gp = ghs + p * 64 * GHS + b * GHS;
                    a0 += gp[gxc];
                    a1 += gp[8 + gxc];
                    a2 += gp[16 + gxc];
                }
                const size_t rowbt = (size_t)b * Tsz + t;
                const float rg = 1.0f / (1.0f + expf(-(pxr[r] + a0 + br)));
                const float zg = 1.0f / (1.0f + expf(-(pxz[r] + a1 + bz)));
                const float ng = tanhf(pxn[r] + rg * (a2 + bn));
                const float hnew = (1.0f - zg) * ng + zg * phold[r];
                hfOut[(size_t)b * Hsz + jcol] = hnew;
                __nv_bfloat16 hh = __float2bfloat16(hnew);
                __nv_bfloat16 hl = __float2bfloat16(hnew - __bfloat162float(hh));
                hHiOut[(size_t)b * Hsz + jcol] = hh;
                hLoOut[(size_t)b * Hsz + jcol] = hl;
                yHi[rowbt * Hsz + jcol] = hh;
                yLo[rowbt * Hsz + jcol] = hl;
            }
        }

        // ---- grid barrier ----
        __syncthreads();
        if (tid == 0) {
            __threadfence();
            atomicAdd(&g_bar, 1u);
            const unsigned target = (unsigned)NBLK * (unsigned)(t_base + t + 1);
            unsigned v;
            do {
                asm volatile("ld.global.acquire.gpu.u32 %0, [%1];"
                             : "=r"(v) : "l"(&g_bar));
            } while (v < target);
        }
        __syncthreads();
    }
}

// ---------------- launch ------------------------------------------------------
extern "C" void kernel_launch(void* const* d_in, const int* in_sizes, int n_in,
                              void* d_out, int out_size)
{
    const int*   X     = (const int*)d_in[0];
    const float* h0    = (const float*)d_in[1];
    const float* emb   = (const float*)d_in[2];
    const float* W_ih  = (const float*)d_in[3];
    const float* W_hh  = (const float*)d_in[4];
    const float* b_ih  = (const float*)d_in[5];
    const float* b_hh  = (const float*)d_in[6];
    const float* W_out = (const float*)d_in[7];
    const float* b_out = (const float*)d_in[8];
    float* out = (float*)d_out;

    float *pM0, *pgx, *phFA, *phFB;
    __nv_bfloat16 *pyHi, *pyLo, *phHiA, *phHiB, *phLoA, *phLoB;
    cudaGetSymbolAddress((void**)&pM0,  g_M0);
    cudaGetSymbolAddress((void**)&pgx,  g_gx);
    cudaGetSymbolAddress((void**)&pyHi, g_yHi);
    cudaGetSymbolAddress((void**)&pyLo, g_yLo);
    cudaGetSymbolAddress((void**)&phFA, g_hFA);
    cudaGetSymbolAddress((void**)&phFB, g_hFB);
    cudaGetSymbolAddress((void**)&phHiA, g_hHiA);
    cudaGetSymbolAddress((void**)&phHiB, g_hHiB);
    cudaGetSymbolAddress((void**)&phLoA, g_hLoA);
    cudaGetSymbolAddress((void**)&phLoB, g_hLoB);

    cudaFuncSetAttribute(gru_scan_mma,
                         cudaFuncAttributeMaxDynamicSharedMemorySize, SCAN_SMEM_B);

    // 1) h0 split for layer 0
    hinit_kernel<<<Bsz * Hsz / 256, 256>>>(h0, phFA, phHiA, phLoA);

    // 2) M0T[v,g] = emb[v].W_ih0[g] + b_ih0[g]  (also zeroes grid barrier)
    {
        dim3 grid(G3 / 128, Vsz / 128);
        gemm_tn_128<<<grid, 256>>>(emb, W_ih, b_ih, pM0, Vsz, G3, Hsz);
    }

    // 3) gx0 gather
    gx0_fill_kernel<<<(Bsz * Tsz * (G3 / 4)) / 256, 256>>>(X);

    // 4) layer-0 scan  (4th launch -> ncu capture slot)
    gru_scan_mma<<<NBLK, 256, SCAN_SMEM_B>>>(W_hh, b_hh, pgx, pyHi, pyLo,
                                             phFA, phFB, phHiA, phHiB, phLoA, phLoB, 0);

    // 5) gx1 = y0 @ W_ih1^T + b_ih1
    {
        dim3 grid(G3 / 64, (Bsz * Tsz) / 128);
        mma_gemm<<<grid, 256>>>(pyHi, pyLo, W_ih + (size_t)G3 * Hsz, b_ih + G3,
                                pgx, Bsz * Tsz, G3, 0);
    }

    // 6) layer-1 scan
    hinit_kernel<<<Bsz * Hsz / 256, 256>>>(h0 + Bsz * Hsz, phFA, phHiA, phLoA);
    gru_scan_mma<<<NBLK, 256, SCAN_SMEM_B>>>(W_hh + (size_t)G3 * Hsz, b_hh + G3,
                                             pgx, pyHi, pyLo,
                                             phFA, phFB, phHiA, phHiB, phLoA, phLoB, Tsz);

    // 7) logits for t < T-1 (row remap skips last timestep)
    {
        int M = Bsz * (Tsz - 1);                 // 32704
        dim3 grid(Vsz / 64, (M + 127) / 128);
        mma_gemm<<<grid, 256>>>(pyHi, pyLo, W_out, b_out, out, M, Vsz, 1);
    }
}

// round 12
// speedup vs baseline: 1.0235x; 1.0235x over previous
#include <cuda_runtime.h>
#include <cuda_bf16.h>
#include <math.h>

// Problem constants
#define Bsz 64
#define Tsz 512
#define Vsz 256
#define Hsz 1024
#define G3  3072   // 3*H
#define NBLK 128
#define NTHR 512

#define SWPAD 1032       // W strip row stride (bf16) -> ldmatrix conflict-free
#define CHPAD 40         // h k32-chunk row stride (bf16) = 80B -> conflict-free
#define CHBUF (64 * CHPAD)   // one (grp,buf,arr) chunk buffer (bf16 elems)
#define GHS   25
// SMEM: W hi/lo (99072) + h [4 grp][2 buf][2 arr][CHBUF] (81920) + ghs[4][64*GHS] (25600)
#define SCAN_SMEM_B (24*SWPAD*2*2 + 4*2*2*CHBUF*2 + 4*64*GHS*4)   // 206592 B

typedef unsigned long long ull;

// ---------------- mma.sync helpers ------------------------------------------
__device__ __forceinline__ void mma_bf16(float* c, const unsigned* a, const unsigned* b) {
    asm volatile(
        "mma.sync.aligned.m16n8k16.row.col.f32.bf16.bf16.f32 "
        "{%0,%1,%2,%3}, {%4,%5,%6,%7}, {%8,%9}, {%0,%1,%2,%3};\n"
        : "+f"(c[0]), "+f"(c[1]), "+f"(c[2]), "+f"(c[3])
        : "r"(a[0]), "r"(a[1]), "r"(a[2]), "r"(a[3]), "r"(b[0]), "r"(b[1]));
}
__device__ __forceinline__ void ldsm4(unsigned* r, const void* p) {
    unsigned a = (unsigned)__cvta_generic_to_shared(p);
    asm volatile("ldmatrix.sync.aligned.m8n8.x4.shared.b16 {%0,%1,%2,%3}, [%4];"
                 : "=r"(r[0]), "=r"(r[1]), "=r"(r[2]), "=r"(r[3]) : "r"(a));
}
__device__ __forceinline__ unsigned pack_bf16x2(__nv_bfloat16 a, __nv_bfloat16 b) {
    __nv_bfloat162 t; t.x = a; t.y = b;
    return *(unsigned*)&t;
}

// packed fp32x2 FMA (kept for the fp32 M0 GEMM)
__device__ __forceinline__ void ffma2(ull& d, ull a, ull b) {
    asm("fma.rn.f32x2 %0, %1, %2, %0;" : "+l"(d) : "l"(a), "l"(b));
}
__device__ __forceinline__ ull pack_rep(float v) {
    ull r; unsigned u = __float_as_uint(v);
    asm("mov.b64 %0, {%1, %1};" : "=l"(r) : "r"(u));
    return r;
}
__device__ __forceinline__ float2 unpack2(ull v) {
    float2 r;
    asm("mov.b64 {%0, %1}, %2;" : "=f"(r.x), "=f"(r.y) : "l"(v));
    return r;
}

// ---------------- scratch (static __device__, no allocations) ----------------
__device__ float g_M0[(size_t)Vsz * G3];
__device__ float g_gx[(size_t)Bsz * Tsz * G3];
__device__ __nv_bfloat16 g_yHi[(size_t)Bsz * Tsz * Hsz];
__device__ __nv_bfloat16 g_yLo[(size_t)Bsz * Tsz * Hsz];
__device__ float g_hFA[Bsz * Hsz];
__device__ float g_hFB[Bsz * Hsz];
__device__ __nv_bfloat16 g_hHiA[Bsz * Hsz], g_hHiB[Bsz * Hsz];
__device__ __nv_bfloat16 g_hLoA[Bsz * Hsz], g_hLoB[Bsz * Hsz];
__device__ unsigned g_bar;

// ---------------- h0 init: fp32 copy + bf16 hi/lo split ----------------------
__global__ __launch_bounds__(256) void hinit_kernel(
    const float* __restrict__ src, float* __restrict__ hf,
    __nv_bfloat16* __restrict__ hhi, __nv_bfloat16* __restrict__ hlo)
{
    int i = blockIdx.x * 256 + threadIdx.x;
    float f = src[i];
    hf[i] = f;
    __nv_bfloat16 h = __float2bfloat16(f);
    hhi[i] = h;
    hlo[i] = __float2bfloat16(f - __bfloat162float(h));
}

// ---------------- fp32 GEMM 128x128x16, f32x2 (M0 only; also zeroes g_bar) ---
__global__ __launch_bounds__(256, 2) void gemm_tn_128(
    const float* __restrict__ A, const float* __restrict__ B,
    const float* __restrict__ bias, float* __restrict__ C,
    int M, int N, int K)
{
    if (blockIdx.x == 0 && blockIdx.y == 0 && threadIdx.x == 0) g_bar = 0u;

    __shared__ float As[16 * 128];
    __shared__ float Bs[16 * 128];
    const int tid = threadIdx.x;
    const int m0 = blockIdx.y * 128;
    const int n0 = blockIdx.x * 128;
    const int ty = tid >> 4;
    const int tx = tid & 15;
    const int lr = tid >> 1;
    const int lk = (tid & 1) << 3;

    const float* Ap = A + (size_t)(m0 + lr) * K + lk;
    const float* Bp = B + (size_t)(n0 + lr) * K + lk;

    ull acc[8][4];
#pragma unroll
    for (int i = 0; i < 8; ++i)
#pragma unroll
        for (int j = 0; j < 4; ++j) acc[i][j] = 0ull;

    float4 pa0 = *(const float4*)Ap;
    float4 pa1 = *(const float4*)(Ap + 4);
    float4 pb0 = *(const float4*)Bp;
    float4 pb1 = *(const float4*)(Bp + 4);

    const int nch = K >> 4;
    for (int c = 0; c < nch; ++c) {
        As[(lk + 0) * 128 + lr] = pa0.x; As[(lk + 1) * 128 + lr] = pa0.y;
        As[(lk + 2) * 128 + lr] = pa0.z; As[(lk + 3) * 128 + lr] = pa0.w;
        As[(lk + 4) * 128 + lr] = pa1.x; As[(lk + 5) * 128 + lr] = pa1.y;
        As[(lk + 6) * 128 + lr] = pa1.z; As[(lk + 7) * 128 + lr] = pa1.w;
        Bs[(lk + 0) * 128 + lr] = pb0.x; Bs[(lk + 1) * 128 + lr] = pb0.y;
        Bs[(lk + 2) * 128 + lr] = pb0.z; Bs[(lk + 3) * 128 + lr] = pb0.w;
        Bs[(lk + 4) * 128 + lr] = pb1.x; Bs[(lk + 5) * 128 + lr] = pb1.y;
        Bs[(lk + 6) * 128 + lr] = pb1.z; Bs[(lk + 7) * 128 + lr] = pb1.w;
        __syncthreads();
        if (c + 1 < nch) {
            pa0 = *(const float4*)(Ap + (c + 1) * 16);
            pa1 = *(const float4*)(Ap + (c + 1) * 16 + 4);
            pb0 = *(const float4*)(Bp + (c + 1) * 16);
            pb1 = *(const float4*)(Bp + (c + 1) * 16 + 4);
        }
#pragma unroll
        for (int k = 0; k < 16; ++k) {
            float4 a0 = *(const float4*)&As[k * 128 + (ty << 2)];
            float4 a1 = *(const float4*)&As[k * 128 + (ty << 2) + 64];
            ulonglong2 b0 = *(const ulonglong2*)&Bs[k * 128 + (tx << 2)];
            ulonglong2 b1 = *(const ulonglong2*)&Bs[k * 128 + (tx << 2) + 64];
            ull ap[8];
            ap[0] = pack_rep(a0.x); ap[1] = pack_rep(a0.y);
            ap[2] = pack_rep(a0.z); ap[3] = pack_rep(a0.w);
            ap[4] = pack_rep(a1.x); ap[5] = pack_rep(a1.y);
            ap[6] = pack_rep(a1.z); ap[7] = pack_rep(a1.w);
#pragma unroll
            for (int i = 0; i < 8; ++i) {
                ffma2(acc[i][0], ap[i], b0.x);
                ffma2(acc[i][1], ap[i], b0.y);
                ffma2(acc[i][2], ap[i], b1.x);
                ffma2(acc[i][3], ap[i], b1.y);
            }
        }
        __syncthreads();
    }

    float bb[8];
#pragma unroll
    for (int j = 0; j < 4; ++j) {
        bb[j]     = bias[n0 + (tx << 2) + j];
        bb[4 + j] = bias[n0 + (tx << 2) + 64 + j];
    }
#pragma unroll
    for (int i = 0; i < 8; ++i) {
        int row = m0 + (ty << 2) + (i & 3) + ((i >> 2) << 6);
        float* Cp = C + (size_t)row * N + n0 + (tx << 2);
        float2 c0 = unpack2(acc[i][0]);
        float2 c1 = unpack2(acc[i][1]);
        float2 c2 = unpack2(acc[i][2]);
        float2 c3 = unpack2(acc[i][3]);
        float4 v0 = make_float4(c0.x + bb[0], c0.y + bb[1], c1.x + bb[2], c1.y + bb[3]);
        float4 v1 = make_float4(c2.x + bb[4], c2.y + bb[5], c3.x + bb[6], c3.y + bb[7]);
        *(float4*)Cp = v0;
        *(float4*)(Cp + 64) = v1;
    }
}

// ---------------- gx0 gather: gx0[bt, g] = M0T[X[bt], g] ---------------------
__global__ __launch_bounds__(256) void gx0_fill_kernel(const int* __restrict__ X)
{
    size_t idx = (size_t)blockIdx.x * 256 + threadIdx.x;
    int bt = (int)(idx / (G3 / 4));
    int gq = (int)(idx % (G3 / 4));
    int tok = X[bt];
    float4 v = ((const float4*)g_M0)[(size_t)tok * (G3 / 4) + gq];
    ((float4*)g_gx)[idx] = v;
}

// ---------------- bf16-split MMA GEMM: C[M,N] = Y @ B^T + bias ---------------
__global__ __launch_bounds__(256) void mma_gemm(
    const __nv_bfloat16* __restrict__ Ahi, const __nv_bfloat16* __restrict__ Alo,
    const float* __restrict__ B, const float* __restrict__ bias,
    float* __restrict__ C, int M, int N, int remapA)
{
    __shared__ __nv_bfloat16 sAhi[128 * 40], sAlo[128 * 40];
    __shared__ __nv_bfloat16 sBhi[64 * 40],  sBlo[64 * 40];
    const int tid = threadIdx.x, wid = tid >> 5, lane = tid & 31;
    const int m0 = blockIdx.y * 128, n0 = blockIdx.x * 64;
    const int wm = wid & 3, wn = wid >> 2;

    float acc[2][4][4];
#pragma unroll
    for (int mt = 0; mt < 2; ++mt)
#pragma unroll
        for (int nt = 0; nt < 4; ++nt)
#pragma unroll
            for (int q = 0; q < 4; ++q) acc[mt][nt][q] = 0.f;

    for (int c = 0; c < 32; ++c) {
        const int k0 = c * 32;
#pragma unroll
        for (int s = 0; s < 4; ++s) {
            int i = tid + s * 256;
            int arr = i >> 9, e = i & 511, row = e >> 2, q = e & 3;
            int r = m0 + row; if (r >= M) r = M - 1;
            if (remapA) r = (r / (Tsz - 1)) * Tsz + (r % (Tsz - 1));
            const __nv_bfloat16* src = arr ? Alo : Ahi;
            uint4 v = *(const uint4*)(src + (size_t)r * Hsz + k0 + q * 8);
            __nv_bfloat16* dst = (arr ? sAlo : sAhi) + row * 40 + q * 8;
            *(uint4*)dst = v;
        }
#pragma unroll
        for (int s = 0; s < 2; ++s) {
            int i = tid + s * 256;
            int row = i >> 3, q = i & 7;
            float4 v = *(const float4*)(B + (size_t)(n0 + row) * Hsz + k0 + q * 4);
            __nv_bfloat16 h0 = __float2bfloat16(v.x), h1 = __float2bfloat16(v.y);
            __nv_bfloat16 h2 = __float2bfloat16(v.z), h3 = __float2bfloat16(v.w);
            __nv_bfloat16 l0 = __float2bfloat16(v.x - __bfloat162float(h0));
            __nv_bfloat16 l1 = __float2bfloat16(v.y - __bfloat162float(h1));
            __nv_bfloat16 l2 = __float2bfloat16(v.z - __bfloat162float(h2));
            __nv_bfloat16 l3 = __float2bfloat16(v.w - __bfloat162float(h3));
            unsigned* dh = (unsigned*)(sBhi + row * 40 + q * 4);
            dh[0] = pack_bf16x2(h0, h1); dh[1] = pack_bf16x2(h2, h3);
            unsigned* dl = (unsigned*)(sBlo + row * 40 + q * 4);
            dl[0] = pack_bf16x2(l0, l1); dl[1] = pack_bf16x2(l2, l3);
        }
        __syncthreads();

        unsigned bh[4][4], bl[4][4];
#pragma unroll
        for (int nt = 0; nt < 4; ++nt) {
            const int brow = wn * 32 + nt * 8 + (lane & 7);
            ldsm4(bh[nt], sBhi + brow * 40 + ((lane >> 3) << 3));
            ldsm4(bl[nt], sBlo + brow * 40 + ((lane >> 3) << 3));
        }
#pragma unroll
        for (int kk = 0; kk < 2; ++kk) {
            unsigned ah[2][4], al[2][4];
#pragma unroll
            for (int mt = 0; mt < 2; ++mt) {
                const int aoff = (wm * 32 + mt * 16 + (lane & 15)) * 40 + kk * 16 + ((lane >> 4) << 3);
                ldsm4(ah[mt], sAhi + aoff);
                ldsm4(al[mt], sAlo + aoff);
            }
#pragma unroll
            for (int mt = 0; mt < 2; ++mt)
#pragma unroll
                for (int nt = 0; nt < 4; ++nt) {
                    mma_bf16(acc[mt][nt], ah[mt], bh[nt] + 2 * kk);
                    mma_bf16(acc[mt][nt], ah[mt], bl[nt] + 2 * kk);
                    mma_bf16(acc[mt][nt], al[mt], bh[nt] + 2 * kk);
                }
        }
        __syncthreads();
    }

#pragma unroll
    for (int mt = 0; mt < 2; ++mt)
#pragma unroll
        for (int nt = 0; nt < 4; ++nt) {
            int r0 = m0 + wm * 32 + mt * 16 + (lane >> 2);
            int cb = n0 + wn * 32 + nt * 8 + 2 * (lane & 3);
            float b0 = bias[cb], b1 = bias[cb + 1];
            if (r0 < M) {
                C[(size_t)r0 * N + cb]     = acc[mt][nt][0] + b0;
                C[(size_t)r0 * N + cb + 1] = acc[mt][nt][1] + b1;
            }
            int r1 = r0 + 8;
            if (r1 < M) {
                C[(size_t)r1 * N + cb]     = acc[mt][nt][2] + b0;
                C[(size_t)r1 * N + cb + 1] = acc[mt][nt][3] + b1;
            }
        }
}

// ---------------- persistent GRU scan (16 warps = 4m x 4k, bf16 MMA) ---------
// 512 threads. Each warp: m16 tile x k256 quarter, all 3 gates. Both k16 A
// fragments per k32 chunk loaded (kk*16 offset — fixes the R11 bug).
__global__ __launch_bounds__(NTHR) void gru_scan_mma(
    const float* __restrict__ Whh, const float* __restrict__ bhh,
    const float* __restrict__ gx,
    __nv_bfloat16* __restrict__ yHi, __nv_bfloat16* __restrict__ yLo,
    float* __restrict__ hfA, float* __restrict__ hfB,
    __nv_bfloat16* __restrict__ hHiA, __nv_bfloat16* __restrict__ hHiB,
    __nv_bfloat16* __restrict__ hLoA, __nv_bfloat16* __restrict__ hLoB,
    int t_base)
{
    extern __shared__ __align__(16) unsigned char smraw[];
    __nv_bfloat16* sWhi = (__nv_bfloat16*)smraw;            // [24][SWPAD]
    __nv_bfloat16* sWlo = sWhi + 24 * SWPAD;
    __nv_bfloat16* sH   = sWlo + 24 * SWPAD;                // [4 grp][2 buf][2 arr][CHBUF]
    float* ghs = (float*)(sH + 16 * CHBUF);                 // [4][64*GHS]

    const int tid = threadIdx.x, wid = tid >> 5, lane = tid & 31;
    const int c0 = blockIdx.x << 3;
    const int mw = wid & 3, kc = wid >> 2;
    const int gtid = tid & 127, grp = tid >> 7;             // staging group == kc

    // Convert W strip to bf16 hi/lo in SMEM once per layer.
    for (int i = tid; i < 24 * 1024; i += NTHR) {
        int r = i >> 10, k = i & 1023;
        int g = r >> 3, jj = r & 7;
        float f = Whh[(size_t)(g * Hsz + c0 + jj) * Hsz + k];
        __nv_bfloat16 h = __float2bfloat16(f);
        sWhi[r * SWPAD + k] = h;
        sWlo[r * SWPAD + k] = __float2bfloat16(f - __bfloat162float(h));
    }
    const int gy = (tid & 255) >> 3, gxc = tid & 7;
    const int jcol = c0 + gxc;
    const float br = bhh[jcol];
    const float bz = bhh[Hsz + jcol];
    const float bn = bhh[2 * Hsz + jcol];
    __syncthreads();

    for (int t = 0; t < Tsz; ++t) {
        const int par = t & 1;
        const float* hfIn  = par ? hfB : hfA;
        float*       hfOut = par ? hfA : hfB;
        const __nv_bfloat16* hHiIn = par ? hHiB : hHiA;
        const __nv_bfloat16* hLoIn = par ? hLoB : hLoA;
        __nv_bfloat16* hHiOut = par ? hHiA : hHiB;
        __nv_bfloat16* hLoOut = par ? hLoA : hLoB;

        const int kq0 = grp * 256;                // this group's k base

        uint4 stg[4];
        // stage chunk 0 (k32) of this group's k-quarter
#pragma unroll
        for (int s = 0; s < 4; ++s) {
            int idx = gtid + s * 128;             // 0..511
            int arr = idx >> 8, e = idx & 255, row = e >> 2, q = e & 3;
            const __nv_bfloat16* src = arr ? hLoIn : hHiIn;
            stg[s] = __ldcg((const uint4*)(src + (size_t)row * Hsz + kq0) + q);
        }
        // prefetch gate preacts + h_old (threads 0..255; consumed at step end)
        float pxr[2], pxz[2], pxn[2], phold[2];
        if (tid < 256) {
#pragma unroll
            for (int r = 0; r < 2; ++r) {
                const int b = gy + (r << 5);
                const float* gxr = gx + ((size_t)b * Tsz + t) * G3;
                pxr[r] = __ldcg(gxr + jcol);
                pxz[r] = __ldcg(gxr + Hsz + jcol);
                pxn[r] = __ldcg(gxr + 2 * Hsz + jcol);
                phold[r] = hfIn[(size_t)b * Hsz + jcol];
            }
        }
#pragma unroll
        for (int s = 0; s < 4; ++s) {
            int idx = gtid + s * 128;
            int arr = idx >> 8, e = idx & 255, row = e >> 2, q = e & 3;
            __nv_bfloat16* dst = sH + ((grp * 2 + 0) * 2 + arr) * CHBUF + row * CHPAD + q * 8;
            *(uint4*)dst = stg[s];
        }
        asm volatile("bar.sync %0, 128;" :: "r"(grp + 1) : "memory");

        float accP[3][4], accQ[3][4];
#pragma unroll
        for (int g = 0; g < 3; ++g)
#pragma unroll
            for (int q = 0; q < 4; ++q) { accP[g][q] = 0.f; accQ[g][q] = 0.f; }

        for (int it = 0; it < 8; ++it) {
            if (it < 7) {
#pragma unroll
                for (int s = 0; s < 4; ++s) {
                    int idx = gtid + s * 128;
                    int arr = idx >> 8, e = idx & 255, row = e >> 2, q = e & 3;
                    const __nv_bfloat16* src = arr ? hLoIn : hHiIn;
                    stg[s] = __ldcg((const uint4*)(src + (size_t)row * Hsz + kq0 + (it + 1) * 32) + q);
                }
            }
            const int buf = it & 1;
            const __nv_bfloat16* Hh = sH + ((grp * 2 + buf) * 2 + 0) * CHBUF;
            const __nv_bfloat16* Hl = sH + ((grp * 2 + buf) * 2 + 1) * CHBUF;
            const int kbase = kq0 + it * 32;

            unsigned bh[3][4], bl[3][4];
#pragma unroll
            for (int g = 0; g < 3; ++g) {
                const int woff = (g * 8 + (lane & 7)) * SWPAD + kbase + ((lane >> 3) << 3);
                ldsm4(bh[g], sWhi + woff);
                ldsm4(bl[g], sWlo + woff);
            }
            unsigned ah[2][4], al[2][4];
#pragma unroll
            for (int kk = 0; kk < 2; ++kk) {
                const int aoff = (mw * 16 + (lane & 15)) * CHPAD + kk * 16 + ((lane >> 4) << 3);
                ldsm4(ah[kk], Hh + aoff);
                ldsm4(al[kk], Hl + aoff);
            }
#pragma unroll
            for (int kk = 0; kk < 2; ++kk) {
#pragma unroll
                for (int g = 0; g < 3; ++g) {
                    mma_bf16(accP[g], ah[kk], bh[g] + 2 * kk);
                    mma_bf16(accQ[g], ah[kk], bl[g] + 2 * kk);
                    mma_bf16(accQ[g], al[kk], bh[g] + 2 * kk);
                }
            }
            if (it < 7) {
#pragma unroll
                for (int s = 0; s < 4; ++s) {
                    int idx = gtid + s * 128;
                    int arr = idx >> 8, e = idx & 255, row = e >> 2, q = e & 3;
                    __nv_bfloat16* dst = sH + ((grp * 2 + ((it + 1) & 1)) * 2 + arr) * CHBUF
                                       + row * CHPAD + q * 8;
                    *(uint4*)dst = stg[s];
                }
                asm volatile("bar.sync %0, 128;" :: "r"(grp + 1) : "memory");
            }
        }

        // write k-partial gh preacts to SMEM
        {
            float* gp = ghs + kc * 64 * GHS;
            int row = mw * 16 + (lane >> 2);
#pragma unroll
            for (int g = 0; g < 3; ++g) {
                int gcol = g * 8 + 2 * (lane & 3);
                gp[row * GHS + gcol]           = accP[g][0] + accQ[g][0];
                gp[row * GHS + gcol + 1]       = accP[g][1] + accQ[g][1];
                gp[(row + 8) * GHS + gcol]     = accP[g][2] + accQ[g][2];
                gp[(row + 8) * GHS + gcol + 1] = accP[g][3] + accQ[g][3];
            }
        }
        __syncthreads();

        // gates + state update (threads 0..255; sum 4 k-partials)
        if (tid < 256) {
#pragma unroll
            for (int r = 0; r < 2; ++r) {
                const int b = gy + (r << 5);
                float a0 = 0.f, a1 = 0.f, a2 = 0.f;
#pragma unroll
                for (int p = 0; p < 4; ++p) {
                    const float* gp = ghs + p * 64 * GHS + b * GHS;
                    a0 += gp[gxc];
                    a1 += gp[8 + gxc];
                    a2 += gp[16 + gxc];
                }
                const size_t rowbt = (size_t)b * Tsz + t;
                const float rg = 1.0f / (1.0f + expf(-(pxr[r] + a0 + br)));
                const float zg = 1.0f / (1.0f + expf(-(pxz[r] + a1 + bz)));
                const float ng = tanhf(pxn[r] + rg * (a2 + bn));
                const float hnew = (1.0f - zg) * ng + zg * phold[r];
                hfOut[(size_t)b * Hsz + jcol] = hnew;
                __nv_bfloat16 hh = __float2bfloat16(hnew);
                __nv_bfloat16 hl = __float2bfloat16(hnew - __bfloat162float(hh));
                hHiOut[(size_t)b * Hsz + jcol] = hh;
                hLoOut[(size_t)b * Hsz + jcol] = hl;
                yHi[rowbt * Hsz + jcol] = hh;
                yLo[rowbt * Hsz + jcol] = hl;
            }
        }

        // ---- grid barrier ----
        __syncthreads();
        if (tid == 0) {
            __threadfence();
            atomicAdd(&g_bar, 1u);
            const unsigned target = (unsigned)NBLK * (unsigned)(t_base + t + 1);
            unsigned v;
            do {
                asm volatile("ld.global.acquire.gpu.u32 %0, [%1];"
                             : "=r"(v) : "l"(&g_bar));
            } while (v < target);
        }
        __syncthreads();
    }
}

// ---------------- launch ------------------------------------------------------
extern "C" void kernel_launch(void* const* d_in, const int* in_sizes, int n_in,
                              void* d_out, int out_size)
{
    const int*   X     = (const int*)d_in[0];
    const float* h0    = (const float*)d_in[1];
    const float* emb   = (const float*)d_in[2];
    const float* W_ih  = (const float*)d_in[3];
    const float* W_hh  = (const float*)d_in[4];
    const float* b_ih  = (const float*)d_in[5];
    const float* b_hh  = (const float*)d_in[6];
    const float* W_out = (const float*)d_in[7];
    const float* b_out = (const float*)d_in[8];
    float* out = (float*)d_out;

    float *pM0, *pgx, *phFA, *phFB;
    __nv_bfloat16 *pyHi, *pyLo, *phHiA, *phHiB, *phLoA, *phLoB;
    cudaGetSymbolAddress((void**)&pM0,  g_M0);
    cudaGetSymbolAddress((void**)&pgx,  g_gx);
    cudaGetSymbolAddress((void**)&pyHi, g_yHi);
    cudaGetSymbolAddress((void**)&pyLo, g_yLo);
    cudaGetSymbolAddress((void**)&phFA, g_hFA);
    cudaGetSymbolAddress((void**)&phFB, g_hFB);
    cudaGetSymbolAddress((void**)&phHiA, g_hHiA);
    cudaGetSymbolAddress((void**)&phHiB, g_hHiB);
    cudaGetSymbolAddress((void**)&phLoA, g_hLoA);
    cudaGetSymbolAddress((void**)&phLoB, g_hLoB);

    cudaFuncSetAttribute(gru_scan_mma,
                         cudaFuncAttributeMaxDynamicSharedMemorySize, SCAN_SMEM_B);

    // 1) h0 split for layer 0
    hinit_kernel<<<Bsz * Hsz / 256, 256>>>(h0, phFA, phHiA, phLoA);

    // 2) M0T[v,g] = emb[v].W_ih0[g] + b_ih0[g]  (also zeroes grid barrier)
    {
        dim3 grid(G3 / 128, Vsz / 128);
        gemm_tn_128<<<grid, 256>>>(emb, W_ih, b_ih, pM0, Vsz, G3, Hsz);
    }

    // 3) gx0 gather
    gx0_fill_kernel<<<(Bsz * Tsz * (G3 / 4)) / 256, 256>>>(X);

    // 4) layer-0 scan  (4th launch -> ncu capture slot)
    gru_scan_mma<<<NBLK, NTHR, SCAN_SMEM_B>>>(W_hh, b_hh, pgx, pyHi, pyLo,
                                              phFA, phFB, phHiA, phHiB, phLoA, phLoB, 0);

    // 5) gx1 = y0 @ W_ih1^T + b_ih1
    {
        dim3 grid(G3 / 64, (Bsz * Tsz) / 128);
        mma_gemm<<<grid, 256>>>(pyHi, pyLo, W_ih + (size_t)G3 * Hsz, b_ih + G3,
                                pgx, Bsz * Tsz, G3, 0);
    }

    // 6) layer-1 scan
    hinit_kernel<<<Bsz * Hsz / 256, 256>>>(h0 + Bsz * Hsz, phFA, phHiA, phLoA);
    gru_scan_mma<<<NBLK, NTHR, SCAN_SMEM_B>>>(W_hh + (size_t)G3 * Hsz, b_hh + G3,
                                              pgx, pyHi, pyLo,
                                              phFA, phFB, phHiA, phHiB, phLoA, phLoB, Tsz);

    // 7) logits for t < T-1 (row remap skips last timestep)
    {
        int M = Bsz * (Tsz - 1);                 // 32704
        dim3 grid(Vsz / 64, (M + 127) / 128);
        mma_gemm<<<grid, 256>>>(pyHi, pyLo, W_out, b_out, out, M, Vsz, 1);
    }
}

// round 14
// speedup vs baseline: 1.2046x; 1.1770x over previous
#include <cuda_runtime.h>
#include <cuda_bf16.h>
#include <math.h>

// Problem constants
#define Bsz 64
#define Tsz 512
#define Vsz 256
#define Hsz 1024
#define G3  3072   // 3*H
#define NBLK 128

#define SWPAD 1032       // W strip row stride (bf16) -> ldmatrix conflict-free
#define CHPAD 72         // h k64-chunk row stride (bf16)
#define GHS   25
// SMEM: W hi/lo + h [2 grp][2 buf][hi/lo][64*CHPAD] + ghs[2][64*GHS]
#define SCAN_SMEM_B (24*SWPAD*2*2 + 8*64*CHPAD*2 + 2*64*GHS*4)   // 185600 B

typedef unsigned long long ull;

// ---------------- mma.sync helpers ------------------------------------------
__device__ __forceinline__ void mma_bf16(float* c, const unsigned* a, const unsigned* b) {
    asm volatile(
        "mma.sync.aligned.m16n8k16.row.col.f32.bf16.bf16.f32 "
        "{%0,%1,%2,%3}, {%4,%5,%6,%7}, {%8,%9}, {%0,%1,%2,%3};\n"
        : "+f"(c[0]), "+f"(c[1]), "+f"(c[2]), "+f"(c[3])
        : "r"(a[0]), "r"(a[1]), "r"(a[2]), "r"(a[3]), "r"(b[0]), "r"(b[1]));
}
__device__ __forceinline__ void ldsm4(unsigned* r, const void* p) {
    unsigned a = (unsigned)__cvta_generic_to_shared(p);
    asm volatile("ldmatrix.sync.aligned.m8n8.x4.shared.b16 {%0,%1,%2,%3}, [%4];"
                 : "=r"(r[0]), "=r"(r[1]), "=r"(r[2]), "=r"(r[3]) : "r"(a));
}
__device__ __forceinline__ unsigned pack_bf16x2(__nv_bfloat16 a, __nv_bfloat16 b) {
    __nv_bfloat162 t; t.x = a; t.y = b;
    return *(unsigned*)&t;
}

// packed fp32x2 FMA (kept for the fp32 M0 GEMM)
__device__ __forceinline__ void ffma2(ull& d, ull a, ull b) {
    asm("fma.rn.f32x2 %0, %1, %2, %0;" : "+l"(d) : "l"(a), "l"(b));
}
__device__ __forceinline__ ull pack_rep(float v) {
    ull r; unsigned u = __float_as_uint(v);
    asm("mov.b64 %0, {%1, %1};" : "=l"(r) : "r"(u));
    return r;
}
__device__ __forceinline__ float2 unpack2(ull v) {
    float2 r;
    asm("mov.b64 {%0, %1}, %2;" : "=f"(r.x), "=f"(r.y) : "l"(v));
    return r;
}

// ---------------- scratch (static __device__, no allocations) ----------------
__device__ float g_M0[(size_t)Vsz * G3];
__device__ float g_gx[(size_t)Bsz * Tsz * G3];
__device__ __nv_bfloat16 g_yHi[(size_t)Bsz * Tsz * Hsz];
__device__ __nv_bfloat16 g_yLo[(size_t)Bsz * Tsz * Hsz];
__device__ float g_hFA[Bsz * Hsz];
__device__ float g_hFB[Bsz * Hsz];
__device__ __nv_bfloat16 g_h0Hi[Bsz * Hsz];
__device__ __nv_bfloat16 g_h0Lo[Bsz * Hsz];
__device__ unsigned g_bar;

// ---------------- h0 init: fp32 copy + bf16 hi/lo split ----------------------
__global__ __launch_bounds__(256) void hinit_kernel(
    const float* __restrict__ src, float* __restrict__ hf,
    __nv_bfloat16* __restrict__ hhi, __nv_bfloat16* __restrict__ hlo)
{
    int i = blockIdx.x * 256 + threadIdx.x;
    float f = src[i];
    hf[i] = f;
    __nv_bfloat16 h = __float2bfloat16(f);
    hhi[i] = h;
    hlo[i] = __float2bfloat16(f - __bfloat162float(h));
}

// ---------------- fp32 GEMM 128x128x16, f32x2 (M0 only; also zeroes g_bar) ---
__global__ __launch_bounds__(256, 2) void gemm_tn_128(
    const float* __restrict__ A, const float* __restrict__ B,
    const float* __restrict__ bias, float* __restrict__ C,
    int M, int N, int K)
{
    if (blockIdx.x == 0 && blockIdx.y == 0 && threadIdx.x == 0) g_bar = 0u;

    __shared__ float As[16 * 128];
    __shared__ float Bs[16 * 128];
    const int tid = threadIdx.x;
    const int m0 = blockIdx.y * 128;
    const int n0 = blockIdx.x * 128;
    const int ty = tid >> 4;
    const int tx = tid & 15;
    const int lr = tid >> 1;
    const int lk = (tid & 1) << 3;

    const float* Ap = A + (size_t)(m0 + lr) * K + lk;
    const float* Bp = B + (size_t)(n0 + lr) * K + lk;

    ull acc[8][4];
#pragma unroll
    for (int i = 0; i < 8; ++i)
#pragma unroll
        for (int j = 0; j < 4; ++j) acc[i][j] = 0ull;

    float4 pa0 = *(const float4*)Ap;
    float4 pa1 = *(const float4*)(Ap + 4);
    float4 pb0 = *(const float4*)Bp;
    float4 pb1 = *(const float4*)(Bp + 4);

    const int nch = K >> 4;
    for (int c = 0; c < nch; ++c) {
        As[(lk + 0) * 128 + lr] = pa0.x; As[(lk + 1) * 128 + lr] = pa0.y;
        As[(lk + 2) * 128 + lr] = pa0.z; As[(lk + 3) * 128 + lr] = pa0.w;
        As[(lk + 4) * 128 + lr] = pa1.x; As[(lk + 5) * 128 + lr] = pa1.y;
        As[(lk + 6) * 128 + lr] = pa1.z; As[(lk + 7) * 128 + lr] = pa1.w;
        Bs[(lk + 0) * 128 + lr] = pb0.x; Bs[(lk + 1) * 128 + lr] = pb0.y;
        Bs[(lk + 2) * 128 + lr] = pb0.z; Bs[(lk + 3) * 128 + lr] = pb0.w;
        Bs[(lk + 4) * 128 + lr] = pb1.x; Bs[(lk + 5) * 128 + lr] = pb1.y;
        Bs[(lk + 6) * 128 + lr] = pb1.z; Bs[(lk + 7) * 128 + lr] = pb1.w;
        __syncthreads();
        if (c + 1 < nch) {
            pa0 = *(const float4*)(Ap + (c + 1) * 16);
            pa1 = *(const float4*)(Ap + (c + 1) * 16 + 4);
            pb0 = *(const float4*)(Bp + (c + 1) * 16);
            pb1 = *(const float4*)(Bp + (c + 1) * 16 + 4);
        }
#pragma unroll
        for (int k = 0; k < 16; ++k) {
            float4 a0 = *(const float4*)&As[k * 128 + (ty << 2)];
            float4 a1 = *(const float4*)&As[k * 128 + (ty << 2) + 64];
            ulonglong2 b0 = *(const ulonglong2*)&Bs[k * 128 + (tx << 2)];
            ulonglong2 b1 = *(const ulonglong2*)&Bs[k * 128 + (tx << 2) + 64];
            ull ap[8];
            ap[0] = pack_rep(a0.x); ap[1] = pack_rep(a0.y);
            ap[2] = pack_rep(a0.z); ap[3] = pack_rep(a0.w);
            ap[4] = pack_rep(a1.x); ap[5] = pack_rep(a1.y);
            ap[6] = pack_rep(a1.z); ap[7] = pack_rep(a1.w);
#pragma unroll
            for (int i = 0; i < 8; ++i) {
                ffma2(acc[i][0], ap[i], b0.x);
                ffma2(acc[i][1], ap[i], b0.y);
                ffma2(acc[i][2], ap[i], b1.x);
                ffma2(acc[i][3], ap[i], b1.y);
            }
        }
        __syncthreads();
    }

    float bb[8];
#pragma unroll
    for (int j = 0; j < 4; ++j) {
        bb[j]     = bias[n0 + (tx << 2) + j];
        bb[4 + j] = bias[n0 + (tx << 2) + 64 + j];
    }
#pragma unroll
    for (int i = 0; i < 8; ++i) {
        int row = m0 + (ty << 2) + (i & 3) + ((i >> 2) << 6);
        float* Cp = C + (size_t)row * N + n0 + (tx << 2);
        float2 c0 = unpack2(acc[i][0]);
        float2 c1 = unpack2(acc[i][1]);
        float2 c2 = unpack2(acc[i][2]);
        float2 c3 = unpack2(acc[i][3]);
        float4 v0 = make_float4(c0.x + bb[0], c0.y + bb[1], c1.x + bb[2], c1.y + bb[3]);
        float4 v1 = make_float4(c2.x + bb[4], c2.y + bb[5], c3.x + bb[6], c3.y + bb[7]);
        *(float4*)Cp = v0;
        *(float4*)(Cp + 64) = v1;
    }
}

// ---------------- gx0 gather: gx0[bt, g] = M0T[X[bt], g] ---------------------
__global__ __launch_bounds__(256) void gx0_fill_kernel(const int* __restrict__ X)
{
    size_t idx = (size_t)blockIdx.x * 256 + threadIdx.x;
    int bt = (int)(idx / (G3 / 4));
    int gq = (int)(idx % (G3 / 4));
    int tok = X[bt];
    float4 v = ((const float4*)g_M0)[(size_t)tok * (G3 / 4) + gq];
    ((float4*)g_gx)[idx] = v;
}

// ---------------- bf16-split MMA GEMM: C[M,N] = Y @ B^T + bias ---------------
__global__ __launch_bounds__(256) void mma_gemm(
    const __nv_bfloat16* __restrict__ Ahi, const __nv_bfloat16* __restrict__ Alo,
    const float* __restrict__ B, const float* __restrict__ bias,
    float* __restrict__ C, int M, int N, int remapA)
{
    __shared__ __nv_bfloat16 sAhi[128 * 40], sAlo[128 * 40];
    __shared__ __nv_bfloat16 sBhi[64 * 40],  sBlo[64 * 40];
    const int tid = threadIdx.x, wid = tid >> 5, lane = tid & 31;
    const int m0 = blockIdx.y * 128, n0 = blockIdx.x * 64;
    const int wm = wid & 3, wn = wid >> 2;

    float acc[2][4][4];
#pragma unroll
    for (int mt = 0; mt < 2; ++mt)
#pragma unroll
        for (int nt = 0; nt < 4; ++nt)
#pragma unroll
            for (int q = 0; q < 4; ++q) acc[mt][nt][q] = 0.f;

    for (int c = 0; c < 32; ++c) {
        const int k0 = c * 32;
#pragma unroll
        for (int s = 0; s < 4; ++s) {
            int i = tid + s * 256;
            int arr = i >> 9, e = i & 511, row = e >> 2, q = e & 3;
            int r = m0 + row; if (r >= M) r = M - 1;
            if (remapA) r = (r / (Tsz - 1)) * Tsz + (r % (Tsz - 1));
            const __nv_bfloat16* src = arr ? Alo : Ahi;
            uint4 v = *(const uint4*)(src + (size_t)r * Hsz + k0 + q * 8);
            __nv_bfloat16* dst = (arr ? sAlo : sAhi) + row * 40 + q * 8;
            *(uint4*)dst = v;
        }
#pragma unroll
        for (int s = 0; s < 2; ++s) {
            int i = tid + s * 256;
            int row = i >> 3, q = i & 7;
            float4 v = *(const float4*)(B + (size_t)(n0 + row) * Hsz + k0 + q * 4);
            __nv_bfloat16 h0 = __float2bfloat16(v.x), h1 = __float2bfloat16(v.y);
            __nv_bfloat16 h2 = __float2bfloat16(v.z), h3 = __float2bfloat16(v.w);
            __nv_bfloat16 l0 = __float2bfloat16(v.x - __bfloat162float(h0));
            __nv_bfloat16 l1 = __float2bfloat16(v.y - __bfloat162float(h1));
            __nv_bfloat16 l2 = __float2bfloat16(v.z - __bfloat162float(h2));
            __nv_bfloat16 l3 = __float2bfloat16(v.w - __bfloat162float(h3));
            unsigned* dh = (unsigned*)(sBhi + row * 40 + q * 4);
            dh[0] = pack_bf16x2(h0, h1); dh[1] = pack_bf16x2(h2, h3);
            unsigned* dl = (unsigned*)(sBlo + row * 40 + q * 4);
            dl[0] = pack_bf16x2(l0, l1); dl[1] = pack_bf16x2(l2, l3);
        }
        __syncthreads();

        unsigned bh[4][4], bl[4][4];
#pragma unroll
        for (int nt = 0; nt < 4; ++nt) {
            const int brow = wn * 32 + nt * 8 + (lane & 7);
            ldsm4(bh[nt], sBhi + brow * 40 + ((lane >> 3) << 3));
            ldsm4(bl[nt], sBlo + brow * 40 + ((lane >> 3) << 3));
        }
#pragma unroll
        for (int kk = 0; kk < 2; ++kk) {
            unsigned ah[2][4], al[2][4];
#pragma unroll
            for (int mt = 0; mt < 2; ++mt) {
                const int aoff = (wm * 32 + mt * 16 + (lane & 15)) * 40 + kk * 16 + ((lane >> 4) << 3);
                ldsm4(ah[mt], sAhi + aoff);
                ldsm4(al[mt], sAlo + aoff);
            }
#pragma unroll
            for (int mt = 0; mt < 2; ++mt)
#pragma unroll
                for (int nt = 0; nt < 4; ++nt) {
                    mma_bf16(acc[mt][nt], ah[mt], bh[nt] + 2 * kk);
                    mma_bf16(acc[mt][nt], ah[mt], bl[nt] + 2 * kk);
                    mma_bf16(acc[mt][nt], al[mt], bh[nt] + 2 * kk);
                }
        }
        __syncthreads();
    }

#pragma unroll
    for (int mt = 0; mt < 2; ++mt)
#pragma unroll
        for (int nt = 0; nt < 4; ++nt) {
            int r0 = m0 + wm * 32 + mt * 16 + (lane >> 2);
            int cb = n0 + wn * 32 + nt * 8 + 2 * (lane & 3);
            float b0 = bias[cb], b1 = bias[cb + 1];
            if (r0 < M) {
                C[(size_t)r0 * N + cb]     = acc[mt][nt][0] + b0;
                C[(size_t)r0 * N + cb + 1] = acc[mt][nt][1] + b1;
            }
            int r1 = r0 + 8;
            if (r1 < M) {
                C[(size_t)r1 * N + cb]     = acc[mt][nt][2] + b0;
                C[(size_t)r1 * N + cb + 1] = acc[mt][nt][3] + b1;
            }
        }
}

// ---------------- persistent GRU scan (R9 layout; h staged from y) -----------
// 256 threads, 8 warps = 4 m-tiles x 2 k-halves. Each warp computes ALL 3
// gates for its m16 over k512. h(t) read from yHi/yLo column t-1 (t=0 from
// h0 split arrays) — no separate hHi/hLo ping-pong, 2 fewer stores per row.
__global__ __launch_bounds__(256) void gru_scan_mma(
    const float* __restrict__ Whh, const float* __restrict__ bhh,
    const float* __restrict__ gx,
    __nv_bfloat16* __restrict__ yHi, __nv_bfloat16* __restrict__ yLo,
    float* __restrict__ hfA, float* __restrict__ hfB,
    const __nv_bfloat16* __restrict__ h0Hi, const __nv_bfloat16* __restrict__ h0Lo,
    int t_base)
{
    extern __shared__ __align__(16) unsigned char smraw[];
    __nv_bfloat16* sWhi = (__nv_bfloat16*)smraw;            // [24][SWPAD]
    __nv_bfloat16* sWlo = sWhi + 24 * SWPAD;
    __nv_bfloat16* sH   = sWlo + 24 * SWPAD;                // [grp][buf][hi/lo][64*CHPAD]
    float* ghs = (float*)(sH + 8 * 64 * CHPAD);             // [2][64*GHS]

    const int tid = threadIdx.x, wid = tid >> 5, lane = tid & 31;
    const int c0 = blockIdx.x << 3;
    const int mw = wid & 3, kc = wid >> 2;
    const int gtid = tid & 127, grp = tid >> 7;             // staging group == kc

    // Convert W strip to bf16 hi/lo in SMEM once per layer.
    for (int i = tid; i < 24 * 1024; i += 256) {
        int r = i >> 10, k = i & 1023;
        int g = r >> 3, jj = r & 7;
        float f = Whh[(size_t)(g * Hsz + c0 + jj) * Hsz + k];
        __nv_bfloat16 h = __float2bfloat16(f);
        sWhi[r * SWPAD + k] = h;
        sWlo[r * SWPAD + k] = __float2bfloat16(f - __bfloat162float(h));
    }
    const int gy = tid >> 3, gxc = tid & 7;
    const int jcol = c0 + gxc;
    const float br = bhh[jcol];
    const float bz = bhh[Hsz + jcol];
    const float bn = bhh[2 * Hsz + jcol];
    __syncthreads();

    for (int t = 0; t < Tsz; ++t) {
        const int par = t & 1;
        const float* hfIn  = par ? hfB : hfA;
        float*       hfOut = par ? hfA : hfB;
        // staging source: y column t-1 (row stride Tsz*Hsz) or h0 (stride Hsz)
        const __nv_bfloat16* srcHi = t ? yHi : h0Hi;
        const __nv_bfloat16* srcLo = t ? yLo : h0Lo;
        const size_t rstride = t ? (size_t)Tsz * Hsz : (size_t)Hsz;
        const size_t toff    = t ? (size_t)(t - 1) * Hsz : 0;

        uint4 stg[8];
        // stage chunk 0 of this thread's k-group (k64)
#pragma unroll
        for (int s = 0; s < 8; ++s) {
            int idx = gtid + s * 128;                 // 0..1023
            int arr = idx >> 9, e = idx & 511, row = e >> 3, q = e & 7;
            const __nv_bfloat16* src = arr ? srcLo : srcHi;
            stg[s] = __ldcg((const uint4*)(src + (size_t)row * rstride + toff + grp * 512) + q);
        }
        // prefetch gate preacts + h_old
        float pxr[2], pxz[2], pxn[2], phold[2];
#pragma unroll
        for (int r = 0; r < 2; ++r) {
            const int b = gy + (r << 5);
            const float* gxr = gx + ((size_t)b * Tsz + t) * G3;
            pxr[r] = __ldcg(gxr + jcol);
            pxz[r] = __ldcg(gxr + Hsz + jcol);
            pxn[r] = __ldcg(gxr + 2 * Hsz + jcol);
            phold[r] = hfIn[(size_t)b * Hsz + jcol];
        }
#pragma unroll
        for (int s = 0; s < 8; ++s) {
            int idx = gtid + s * 128;
            int arr = idx >> 9, e = idx & 511, row = e >> 3, q = e & 7;
            __nv_bfloat16* dst = sH + ((grp * 2 + 0) * 2 + arr) * 64 * CHPAD + row * CHPAD + q * 8;
            *(uint4*)dst = stg[s];
        }
        __syncthreads();

        float accP[3][4], accQ[3][4];
#pragma unroll
        for (int g = 0; g < 3; ++g)
#pragma unroll
            for (int q = 0; q < 4; ++q) { accP[g][q] = 0.f; accQ[g][q] = 0.f; }

        for (int it = 0; it < 8; ++it) {
            if (it < 7) {
#pragma unroll
                for (int s = 0; s < 8; ++s) {
                    int idx = gtid + s * 128;
                    int arr = idx >> 9, e = idx & 511, row = e >> 3, q = e & 7;
                    const __nv_bfloat16* src = arr ? srcLo : srcHi;
                    stg[s] = __ldcg((const uint4*)(src + (size_t)row * rstride + toff
                                                   + grp * 512 + (it + 1) * 64) + q);
                }
            }
            const __nv_bfloat16* Hh = sH + ((kc * 2 + (it & 1)) * 2 + 0) * 64 * CHPAD;
            const __nv_bfloat16* Hl = sH + ((kc * 2 + (it & 1)) * 2 + 1) * 64 * CHPAD;
#pragma unroll
            for (int kt = 0; kt < 2; ++kt) {
                const int kabs = kc * 512 + it * 64 + kt * 32;
                unsigned bh[3][4], bl[3][4];
#pragma unroll
                for (int g = 0; g < 3; ++g) {
                    const int woff = (g * 8 + (lane & 7)) * SWPAD + kabs + ((lane >> 3) << 3);
                    ldsm4(bh[g], sWhi + woff);
                    ldsm4(bl[g], sWlo + woff);
                }
#pragma unroll
                for (int kk = 0; kk < 2; ++kk) {
                    unsigned ah[4], al[4];
                    const int aoff = (mw * 16 + (lane & 15)) * CHPAD + kt * 32 + kk * 16 + ((lane >> 4) << 3);
                    ldsm4(ah, Hh + aoff);
                    ldsm4(al, Hl + aoff);
#pragma unroll
                    for (int g = 0; g < 3; ++g) {
                        mma_bf16(accP[g], ah, bh[g] + 2 * kk);
                        mma_bf16(accQ[g], ah, bl[g] + 2 * kk);
                        mma_bf16(accQ[g], al, bh[g] + 2 * kk);
                    }
                }
            }
            if (it < 7) {
#pragma unroll
                for (int s = 0; s < 8; ++s) {
                    int idx = gtid + s * 128;
                    int arr = idx >> 9, e = idx & 511, row = e >> 3, q = e & 7;
                    __nv_bfloat16* dst = sH + ((grp * 2 + ((it + 1) & 1)) * 2 + arr) * 64 * CHPAD
                                       + row * CHPAD + q * 8;
                    *(uint4*)dst = stg[s];
                }
            }
            __syncthreads();
        }

        // write k-partial gh preacts to SMEM
        {
            float* gp = ghs + kc * 64 * GHS;
            int row = mw * 16 + (lane >> 2);
#pragma unroll
            for (int g = 0; g < 3; ++g) {
                int gcol = g * 8 + 2 * (lane & 3);
                gp[row * GHS + gcol]           = accP[g][0] + accQ[g][0];
                gp[row * GHS + gcol + 1]       = accP[g][1] + accQ[g][1];
                gp[(row + 8) * GHS + gcol]     = accP[g][2] + accQ[g][2];
                gp[(row + 8) * GHS + gcol + 1] = accP[g][3] + accQ[g][3];
            }
        }
        __syncthreads();

        // gates + state update (all 256 threads)
        {
            const float* g0 = ghs;
            const float* g1 = ghs + 64 * GHS;
#pragma unroll
            for (int r = 0; r < 2; ++r) {
                const int b = gy + (r << 5);
                const float a0 = g0[b * GHS + gxc]      + g1[b * GHS + gxc];
                const float a1 = g0[b * GHS + 8 + gxc]  + g1[b * GHS + 8 + gxc];
                const float a2 = g0[b * GHS + 16 + gxc] + g1[b * GHS + 16 + gxc];
                const size_t rowbt = (size_t)b * Tsz + t;
                const float rg = 1.0f / (1.0f + expf(-(pxr[r] + a0 + br)));
                const float zg = 1.0f / (1.0f + expf(-(pxz[r] + a1 + bz)));
                const float ng = tanhf(pxn[r] + rg * (a2 + bn));
                const float hnew = (1.0f - zg) * ng + zg * phold[r];
                hfOut[(size_t)b * Hsz + jcol] = hnew;
                __nv_bfloat16 hh = __float2bfloat16(hnew);
                __nv_bfloat16 hl = __float2bfloat16(hnew - __bfloat162float(hh));
                yHi[rowbt * Hsz + jcol] = hh;
                yLo[rowbt * Hsz + jcol] = hl;
            }
        }

        // ---- grid barrier ----
        __syncthreads();
        if (tid == 0) {
            __threadfence();
            atomicAdd(&g_bar, 1u);
            const unsigned target = (unsigned)NBLK * (unsigned)(t_base + t + 1);
            unsigned v;
            do {
                asm volatile("ld.global.acquire.gpu.u32 %0, [%1];"
                             : "=r"(v) : "l"(&g_bar));
            } while (v < target);
        }
        __syncthreads();
    }
}

// ---------------- launch ------------------------------------------------------
extern "C" void kernel_launch(void* const* d_in, const int* in_sizes, int n_in,
                              void* d_out, int out_size)
{
    const int*   X     = (const int*)d_in[0];
    const float* h0    = (const float*)d_in[1];
    const float* emb   = (const float*)d_in[2];
    const float* W_ih  = (const float*)d_in[3];
    const float* W_hh  = (const float*)d_in[4];
    const float* b_ih  = (const float*)d_in[5];
    const float* b_hh  = (const float*)d_in[6];
    const float* W_out = (const float*)d_in[7];
    const float* b_out = (const float*)d_in[8];
    float* out = (float*)d_out;

    float *pM0, *pgx, *phFA, *phFB;
    __nv_bfloat16 *pyHi, *pyLo, *ph0Hi, *ph0Lo;
    cudaGetSymbolAddress((void**)&pM0,  g_M0);
    cudaGetSymbolAddress((void**)&pgx,  g_gx);
    cudaGetSymbolAddress((void**)&pyHi, g_yHi);
    cudaGetSymbolAddress((void**)&pyLo, g_yLo);
    cudaGetSymbolAddress((void**)&phFA, g_hFA);
    cudaGetSymbolAddress((void**)&phFB, g_hFB);
    cudaGetSymbolAddress((void**)&ph0Hi, g_h0Hi);
    cudaGetSymbolAddress((void**)&ph0Lo, g_h0Lo);

    cudaFuncSetAttribute(gru_scan_mma,
                         cudaFuncAttributeMaxDynamicSharedMemorySize, SCAN_SMEM_B);

    // 1) h0 split for layer 0
    hinit_kernel<<<Bsz * Hsz / 256, 256>>>(h0, phFA, ph0Hi, ph0Lo);

    // 2) M0T[v,g] = emb[v].W_ih0[g] + b_ih0[g]  (also zeroes grid barrier)
    {
        dim3 grid(G3 / 128, Vsz / 128);
        gemm_tn_128<<<grid, 256>>>(emb, W_ih, b_ih, pM0, Vsz, G3, Hsz);
    }

    // 3) gx0 gather
    gx0_fill_kernel<<<(Bsz * Tsz * (G3 / 4)) / 256, 256>>>(X);

    // 4) layer-0 scan  (4th launch -> ncu capture slot)
    gru_scan_mma<<<NBLK, 256, SCAN_SMEM_B>>>(W_hh, b_hh, pgx, pyHi, pyLo,
                                             phFA, phFB, ph0Hi, ph0Lo, 0);

    // 5) gx1 = y0 @ W_ih1^T + b_ih1
    {
        dim3 grid(G3 / 64, (Bsz * Tsz) / 128);
        mma_gemm<<<grid, 256>>>(pyHi, pyLo, W_ih + (size_t)G3 * Hsz, b_ih + G3,
                                pgx, Bsz * Tsz, G3, 0);
    }

    // 6) layer-1 scan
    hinit_kernel<<<Bsz * Hsz / 256, 256>>>(h0 + Bsz * Hsz, phFA, ph0Hi, ph0Lo);
    gru_scan_mma<<<NBLK, 256, SCAN_SMEM_B>>>(W_hh + (size_t)G3 * Hsz, b_hh + G3,
                                             pgx, pyHi, pyLo,
                                             phFA, phFB, ph0Hi, ph0Lo, Tsz);

    // 7) logits for t < T-1 (row remap skips last timestep)
    {
        int M = Bsz * (Tsz - 1);                 // 32704
        dim3 grid(Vsz / 64, (M + 127) / 128);
        mma_gemm<<<grid, 256>>>(pyHi, pyLo, W_out, b_out, out, M, Vsz, 1);
    }
}